// round 5
// baseline (speedup 1.0000x reference)
#include <cuda_runtime.h>

#define Bn 128
#define Tn 256
#define Cn 384
#define Hn 64
#define Mtot (Bn*Tn)   // 32768 rows

typedef unsigned int u32;
typedef unsigned short u16;

// scratch (device globals: no allocation allowed)
__device__ float g_q[Mtot*Hn];
__device__ float g_k[Mtot*Hn];
__device__ float g_v[Mtot*Hn];
__device__ u16 g_Whi[Cn*192];   // pre-converted fused weight [384][192] bf16 hi
__device__ u16 g_Wlo[Cn*192];   // residual lo

// ---------------------------------------------------------------------------
// helpers
// ---------------------------------------------------------------------------
__device__ __forceinline__ u32 sptr(const void* p) {
    return (u32)__cvta_generic_to_shared(p);
}
__device__ __forceinline__ void ldm4(u32& r0, u32& r1, u32& r2, u32& r3, u32 a) {
    asm volatile("ldmatrix.sync.aligned.m8n8.x4.shared.b16 {%0,%1,%2,%3},[%4];"
                 : "=r"(r0), "=r"(r1), "=r"(r2), "=r"(r3) : "r"(a));
}
__device__ __forceinline__ void ldm4t(u32& r0, u32& r1, u32& r2, u32& r3, u32 a) {
    asm volatile("ldmatrix.sync.aligned.m8n8.x4.trans.shared.b16 {%0,%1,%2,%3},[%4];"
                 : "=r"(r0), "=r"(r1), "=r"(r2), "=r"(r3) : "r"(a));
}
__device__ __forceinline__ void mma_bf16(float* c, const u32* a, const u32* b) {
    asm volatile(
        "mma.sync.aligned.m16n8k16.row.col.f32.bf16.bf16.f32 "
        "{%0,%1,%2,%3},{%4,%5,%6,%7},{%8,%9},{%0,%1,%2,%3};"
        : "+f"(c[0]), "+f"(c[1]), "+f"(c[2]), "+f"(c[3])
        : "r"(a[0]), "r"(a[1]), "r"(a[2]), "r"(a[3]), "r"(b[0]), "r"(b[1]));
}
__device__ __forceinline__ u32 pack_hi(float a, float b) {
    return (__float_as_uint(a) >> 16) | (__float_as_uint(b) & 0xFFFF0000u);
}
__device__ __forceinline__ u32 pack_lo(float a, float b) {
    float ra = a - __uint_as_float(__float_as_uint(a) & 0xFFFF0000u);
    float rb = b - __uint_as_float(__float_as_uint(b) & 0xFFFF0000u);
    u32 r;
    asm("cvt.rn.bf16x2.f32 %0,%1,%2;" : "=r"(r) : "f"(rb), "f"(ra));
    return r;
}
__device__ __forceinline__ float ex2(float x) {
    float y; asm("ex2.approx.ftz.f32 %0,%1;" : "=f"(y) : "f"(x)); return y;
}
__device__ __forceinline__ void cpa16(u32 dst, const void* src) {
    asm volatile("cp.async.cg.shared.global [%0],[%1],16;" :: "r"(dst), "l"(src));
}
__device__ __forceinline__ void cpa_commit() {
    asm volatile("cp.async.commit_group;");
}
__device__ __forceinline__ void cpa_wait_all() {
    asm volatile("cp.async.wait_group 0;");
}

// ---------------------------------------------------------------------------
// W pre-conversion: [384][64]x3 fp32 -> [384][192] bf16 hi/lo.
// 288 blocks x 256 threads = 73728 = exactly Cn*192.
// ---------------------------------------------------------------------------
__global__ void conv_w(const float* __restrict__ Wq,
                       const float* __restrict__ Wk,
                       const float* __restrict__ Wv)
{
    int i = blockIdx.x * 256 + threadIdx.x;   // 0..73727
    int k = i / 192, n = i % 192;
    const float* W = (n < 64) ? Wq : (n < 128) ? Wk : Wv;
    float v = W[k * 64 + (n & 63)];
    u32 bits = __float_as_uint(v);
    g_Whi[i] = (u16)(bits >> 16);
    float r = v - __uint_as_float(bits & 0xFFFF0000u);
    u16 lo; asm("cvt.rn.bf16.f32 %0,%1;" : "=h"(lo) : "f"(r));
    g_Wlo[i] = lo;
}

// ---------------------------------------------------------------------------
// Fused QKV GEMM, bf16x3: [32768x384] @ [384x192] -> q|k|v.
// grid 512 (M-tiles of 64), 256 threads = 8 warps 2(M)x4(N), warp 32x48.
// K-tile 64. W: cp.async double-buffered from preconverted globals.
// X: LDG prefetch -> convert -> STS, pipelined against mma.
// smem strides: X 72 u16 (144B=9x16B), W 200 u16 (400B=25x16B) -> ldmatrix
// conflict-free. smem total 139264B -> 1 CTA/SM, 8 warps.
// ---------------------------------------------------------------------------
#define XBUF 4608            // 64*72 u16
#define WBUF 12800           // 64*200 u16
#define WBASE (2*2*XBUF)     // 18432 u16
#define QKV_SMEM ((WBASE + 4*WBUF) * 2)   // 139264 bytes

__global__ __launch_bounds__(256) void qkv_fused(const float* __restrict__ x)
{
    extern __shared__ __align__(16) u16 sm[];
    const int tid  = threadIdx.x;
    const int lane = tid & 31;
    const int wid  = tid >> 5;
    const int warp_m = wid >> 2;          // 0..1
    const int warp_n = wid & 3;           // 0..3
    const int g4 = lane >> 2, t4 = lane & 3;
    const int r8 = lane & 7, sel = lane >> 3;
    const int a_row = (sel & 1) * 8 + r8;
    const int a_kof = (sel >> 1) * 8;
    const int bt_krow = (sel & 1) * 8 + r8;
    const int bt_nof  = (sel >> 1) * 8;
    const int m0 = blockIdx.x * 64;

    const u32 smS = sptr(sm);
    // X staging mapping: idx = tid + i*256 -> row = idx>>4, colgroup = idx&15
    const int xrow0 = tid >> 4;           // +16 per i
    const int xcg   = tid & 15;

    float acc[2][6][4];
    #pragma unroll
    for (int mt = 0; mt < 2; mt++)
        #pragma unroll
        for (int nt = 0; nt < 6; nt++)
            #pragma unroll
            for (int e = 0; e < 4; e++) acc[mt][nt][e] = 0.f;

    float4 xv[4];

    // ---- staging lambdas (expanded inline) ----
    auto stageW = [&](int kt, int p) {
        const u16* gH = g_Whi + kt * 64 * 192;
        const u16* gL = g_Wlo + kt * 64 * 192;
        u32 dH = smS + 2u * (WBASE + p * 2 * WBUF);
        u32 dL = dH + 2u * WBUF;
        #pragma unroll
        for (int c = 0; c < 6; c++) {
            int ch = tid + c * 256;        // 0..1535
            int kr = ch / 24, cc = ch % 24;
            u32 o = 2u * (kr * 200 + cc * 8);
            const u16* s = gH + kr * 192 + cc * 8;
            cpa16(dH + o, s);
            cpa16(dL + o, gL + kr * 192 + cc * 8);
        }
        cpa_commit();
    };
    auto loadX = [&](int kt) {
        #pragma unroll
        for (int i = 0; i < 4; i++)
            xv[i] = *(const float4*)(x + (size_t)(m0 + xrow0 + i * 16) * Cn
                                       + kt * 64 + xcg * 4);
    };
    auto convX = [&](int p) {
        u16* XH = sm + p * 2 * XBUF;
        u16* XL = XH + XBUF;
        #pragma unroll
        for (int i = 0; i < 4; i++) {
            int row = xrow0 + i * 16;
            *(uint2*)&XH[row * 72 + xcg * 4] =
                make_uint2(pack_hi(xv[i].x, xv[i].y), pack_hi(xv[i].z, xv[i].w));
            *(uint2*)&XL[row * 72 + xcg * 4] =
                make_uint2(pack_lo(xv[i].x, xv[i].y), pack_lo(xv[i].z, xv[i].w));
        }
    };

    // ---- prologue: tile 0 ----
    stageW(0, 0);
    loadX(0);
    convX(0);
    cpa_wait_all();
    __syncthreads();

    for (int kt = 0; kt < 6; kt++) {
        const int p = kt & 1;
        if (kt < 5) {
            loadX(kt + 1);          // LDG early; hidden under mma
            stageW(kt + 1, p ^ 1);  // cp.async; hidden under mma
        }

        const u32 XH = smS + 2u * (p * 2 * XBUF);
        const u32 XL = XH + 2u * XBUF;
        const u32 WH = smS + 2u * (WBASE + p * 2 * WBUF);
        const u32 WL = WH + 2u * WBUF;

        #pragma unroll
        for (int ks = 0; ks < 4; ks++) {
            const int k0 = ks * 16;
            u32 ah[2][4], al[2][4];
            #pragma unroll
            for (int mt = 0; mt < 2; mt++) {
                u32 off = 2u * ((warp_m * 32 + mt * 16 + a_row) * 72 + k0 + a_kof);
                ldm4(ah[mt][0], ah[mt][1], ah[mt][2], ah[mt][3], XH + off);
                ldm4(al[mt][0], al[mt][1], al[mt][2], al[mt][3], XL + off);
            }
            u32 bh[3][4], bl[3][4];
            #pragma unroll
            for (int h = 0; h < 3; h++) {
                u32 off = 2u * ((k0 + bt_krow) * 200 + warp_n * 48 + h * 16 + bt_nof);
                ldm4t(bh[h][0], bh[h][1], bh[h][2], bh[h][3], WH + off);
                ldm4t(bl[h][0], bl[h][1], bl[h][2], bl[h][3], WL + off);
            }
            #pragma unroll
            for (int mt = 0; mt < 2; mt++)
                #pragma unroll
                for (int h = 0; h < 3; h++)
                    #pragma unroll
                    for (int j = 0; j < 2; j++) {
                        float* c = acc[mt][h * 2 + j];
                        mma_bf16(c, ah[mt], &bh[h][2 * j]);
                        mma_bf16(c, ah[mt], &bl[h][2 * j]);
                        mma_bf16(c, al[mt], &bh[h][2 * j]);
                    }
        }

        if (kt < 5) {
            convX(p ^ 1);     // STS into other buffer (safe: consumed 2 iters ago)
            cpa_wait_all();   // W tile kt+1 arrived
        }
        __syncthreads();
    }

    // ---- epilogue: scatter to g_q / g_k / g_v ----
    #pragma unroll
    for (int mt = 0; mt < 2; mt++) {
        int row = m0 + warp_m * 32 + mt * 16 + g4;
        #pragma unroll
        for (int nt = 0; nt < 6; nt++) {
            int n = warp_n * 48 + nt * 8;
            float* outp = (n < 64) ? g_q : (n < 128) ? g_k : g_v;
            int col = (n & 63) + 2 * t4;
            *(float2*)(outp + (size_t)row       * Hn + col) =
                make_float2(acc[mt][nt][0], acc[mt][nt][1]);
            *(float2*)(outp + (size_t)(row + 8) * Hn + col) =
                make_float2(acc[mt][nt][2], acc[mt][nt][3]);
        }
    }
}

// ---------------------------------------------------------------------------
// Fused causal attention (unchanged from round 4: passing, 26.2us).
// ---------------------------------------------------------------------------
#define ATTN_SMEM (6*9216 + 3*64*4 + 128*4)

__global__ __launch_bounds__(256, 2) void attn_bf16(float* __restrict__ out)
{
    extern __shared__ __align__(16) char smc[];
    u16* Khi  = (u16*)smc;
    u16* Klo  = (u16*)(smc + 9216);
    u16* QPhi = (u16*)(smc + 2 * 9216);
    u16* QPlo = (u16*)(smc + 3 * 9216);
    u16* Vhi  = (u16*)(smc + 4 * 9216);
    u16* Vlo  = (u16*)(smc + 5 * 9216);
    float* m_s = (float*)(smc + 6 * 9216);
    float* l_s = m_s + 64;
    float* f_s = m_s + 128;
    float* pm  = m_s + 192;   // [2][64]

    const int tid  = threadIdx.x;
    const int lane = tid & 31;
    const int wid  = tid >> 5;
    const int warp_m = wid >> 1;
    const int warp_n = wid & 1;
    const int g4 = lane >> 2;
    const int t4 = lane & 3;
    const int r8  = lane & 7;
    const int sel = lane >> 3;
    const int a_row = (sel & 1) * 8 + r8;
    const int a_kof = (sel >> 1) * 8;
    const int bt_krow = (sel & 1) * 8 + r8;
    const int bt_nof  = (sel >> 1) * 8;
    const int bn_row = (sel >> 1) * 8 + r8;
    const int bn_kof = (sel & 1) * 8;

    const int qt = 3 - blockIdx.x;
    const int b  = blockIdx.y;
    const int rowg0 = b * Tn + qt * 64;
    const float SCL = 0.051031036307982884f * 1.4426950408889634f;

    const u32 KhiS = sptr(Khi), KloS = sptr(Klo);
    const u32 QPhiS = sptr(QPhi), QPloS = sptr(QPlo);
    const u32 VhiS = sptr(Vhi), VloS = sptr(Vlo);

    if (tid < 64) { m_s[tid] = -1e30f; l_s[tid] = 0.f; }
    #pragma unroll
    for (int i = 0; i < 4; i++) {
        int idx = tid + i * 256;
        int r = idx >> 4, cg = idx & 15;
        float4 v = *(const float4*)(g_k + (size_t)(rowg0 + r) * Hn + cg * 4);
        u32* H = (u32*)&Khi[r * 72 + cg * 4];
        u32* L = (u32*)&Klo[r * 72 + cg * 4];
        H[0] = pack_hi(v.x, v.y); H[1] = pack_hi(v.z, v.w);
        L[0] = pack_lo(v.x, v.y); L[1] = pack_lo(v.z, v.w);
    }
    __syncthreads();

    const int r0loc = warp_m * 16 + g4;
    float oacc[4][4];
    #pragma unroll
    for (int nt = 0; nt < 4; nt++)
        #pragma unroll
        for (int e = 0; e < 4; e++) oacc[nt][e] = 0.f;

    for (int st = 0; st <= qt; st++) {
        #pragma unroll
        for (int i = 0; i < 4; i++) {
            int idx = tid + i * 256;
            int r = idx >> 4, cg = idx & 15;
            float4 vq = *(const float4*)(g_q + (size_t)(b * Tn + st * 64 + r) * Hn + cg * 4);
            u32* H = (u32*)&QPhi[r * 72 + cg * 4];
            u32* L = (u32*)&QPlo[r * 72 + cg * 4];
            H[0] = pack_hi(vq.x, vq.y); H[1] = pack_hi(vq.z, vq.w);
            L[0] = pack_lo(vq.x, vq.y); L[1] = pack_lo(vq.z, vq.w);
            float4 vv = *(const float4*)(g_v + (size_t)(b * Tn + st * 64 + r) * Hn + cg * 4);
            H = (u32*)&Vhi[r * 72 + cg * 4];
            L = (u32*)&Vlo[r * 72 + cg * 4];
            H[0] = pack_hi(vv.x, vv.y); H[1] = pack_hi(vv.z, vv.w);
            L[0] = pack_lo(vv.x, vv.y); L[1] = pack_lo(vv.z, vv.w);
        }
        __syncthreads();

        float sv[4][4];
        #pragma unroll
        for (int nt = 0; nt < 4; nt++)
            #pragma unroll
            for (int e = 0; e < 4; e++) sv[nt][e] = 0.f;

        #pragma unroll
        for (int ks = 0; ks < 4; ks++) {
            const int k0 = ks * 16;
            u32 ah[4], al[4];
            u32 aoff = 2u * ((warp_m * 16 + a_row) * 72 + k0 + a_kof);
            ldm4(ah[0], ah[1], ah[2], ah[3], KhiS + aoff);
            ldm4(al[0], al[1], al[2], al[3], KloS + aoff);
            u32 bh[2][4], bl[2][4];
            #pragma unroll
            for (int h = 0; h < 2; h++) {
                u32 boff = 2u * ((warp_n * 32 + h * 16 + bn_row) * 72 + k0 + bn_kof);
                ldm4(bh[h][0], bh[h][1], bh[h][2], bh[h][3], QPhiS + boff);
                ldm4(bl[h][0], bl[h][1], bl[h][2], bl[h][3], QPloS + boff);
            }
            #pragma unroll
            for (int h = 0; h < 2; h++)
                #pragma unroll
                for (int j = 0; j < 2; j++) {
                    float* c = sv[h * 2 + j];
                    mma_bf16(c, ah, &bh[h][2 * j]);
                    mma_bf16(c, ah, &bl[h][2 * j]);
                    mma_bf16(c, al, &bh[h][2 * j]);
                }
        }

        #pragma unroll
        for (int nt = 0; nt < 4; nt++)
            #pragma unroll
            for (int e = 0; e < 4; e++) sv[nt][e] *= SCL;
        if (st == qt) {
            #pragma unroll
            for (int nt = 0; nt < 4; nt++) {
                int col = warp_n * 32 + nt * 8 + 2 * t4;
                if (col     > r0loc)     sv[nt][0] = -1e30f;
                if (col + 1 > r0loc)     sv[nt][1] = -1e30f;
                if (col     > r0loc + 8) sv[nt][2] = -1e30f;
                if (col + 1 > r0loc + 8) sv[nt][3] = -1e30f;
            }
        }

        float mx0 = -1e30f, mx1 = -1e30f;
        #pragma unroll
        for (int nt = 0; nt < 4; nt++) {
            mx0 = fmaxf(mx0, fmaxf(sv[nt][0], sv[nt][1]));
            mx1 = fmaxf(mx1, fmaxf(sv[nt][2], sv[nt][3]));
        }
        mx0 = fmaxf(mx0, __shfl_xor_sync(0xffffffffu, mx0, 1));
        mx0 = fmaxf(mx0, __shfl_xor_sync(0xffffffffu, mx0, 2));
        mx1 = fmaxf(mx1, __shfl_xor_sync(0xffffffffu, mx1, 1));
        mx1 = fmaxf(mx1, __shfl_xor_sync(0xffffffffu, mx1, 2));
        if (t4 == 0) {
            pm[warp_n * 64 + r0loc]     = mx0;
            pm[warp_n * 64 + r0loc + 8] = mx1;
        }
        __syncthreads();
        if (tid < 64) {
            float mold = m_s[tid];
            float mnew = fmaxf(mold, fmaxf(pm[tid], pm[64 + tid]));
            float f = ex2(mold - mnew);
            m_s[tid] = mnew; f_s[tid] = f; l_s[tid] *= f;
        }
        __syncthreads();

        float m0 = m_s[r0loc], m1 = m_s[r0loc + 8];
        float f0 = f_s[r0loc], f1 = f_s[r0loc + 8];
        #pragma unroll
        for (int nt = 0; nt < 4; nt++) {
            oacc[nt][0] *= f0; oacc[nt][1] *= f0;
            oacc[nt][2] *= f1; oacc[nt][3] *= f1;
        }
        float ps0 = 0.f, ps1 = 0.f;
        #pragma unroll
        for (int nt = 0; nt < 4; nt++) {
            float p0 = ex2(sv[nt][0] - m0);
            float p1 = ex2(sv[nt][1] - m0);
            float p2 = ex2(sv[nt][2] - m1);
            float p3 = ex2(sv[nt][3] - m1);
            ps0 += p0 + p1; ps1 += p2 + p3;
            int col = warp_n * 32 + nt * 8 + 2 * t4;
            *(u32*)&QPhi[r0loc * 72 + col]       = pack_hi(p0, p1);
            *(u32*)&QPlo[r0loc * 72 + col]       = pack_lo(p0, p1);
            *(u32*)&QPhi[(r0loc + 8) * 72 + col] = pack_hi(p2, p3);
            *(u32*)&QPlo[(r0loc + 8) * 72 + col] = pack_lo(p2, p3);
        }
        ps0 += __shfl_xor_sync(0xffffffffu, ps0, 1);
        ps0 += __shfl_xor_sync(0xffffffffu, ps0, 2);
        ps1 += __shfl_xor_sync(0xffffffffu, ps1, 1);
        ps1 += __shfl_xor_sync(0xffffffffu, ps1, 2);
        if (t4 == 0) {
            pm[warp_n * 64 + r0loc]     = ps0;
            pm[warp_n * 64 + r0loc + 8] = ps1;
        }
        __syncthreads();
        if (tid < 64) l_s[tid] += pm[tid] + pm[64 + tid];

        #pragma unroll
        for (int ks = 0; ks < 4; ks++) {
            const int k0 = ks * 16;
            u32 ah[4], al[4];
            u32 aoff = 2u * ((warp_m * 16 + a_row) * 72 + k0 + a_kof);
            ldm4(ah[0], ah[1], ah[2], ah[3], QPhiS + aoff);
            ldm4(al[0], al[1], al[2], al[3], QPloS + aoff);
            u32 bh[2][4], bl[2][4];
            #pragma unroll
            for (int h = 0; h < 2; h++) {
                u32 boff = 2u * ((k0 + bt_krow) * 72 + warp_n * 32 + h * 16 + bt_nof);
                ldm4t(bh[h][0], bh[h][1], bh[h][2], bh[h][3], VhiS + boff);
                ldm4t(bl[h][0], bl[h][1], bl[h][2], bl[h][3], VloS + boff);
            }
            #pragma unroll
            for (int h = 0; h < 2; h++)
                #pragma unroll
                for (int j = 0; j < 2; j++) {
                    float* c = oacc[h * 2 + j];
                    mma_bf16(c, ah, &bh[h][2 * j]);
                    mma_bf16(c, ah, &bl[h][2 * j]);
                    mma_bf16(c, al, &bh[h][2 * j]);
                }
        }
        __syncthreads();
    }

    float inv0 = 1.f / l_s[r0loc];
    float inv1 = 1.f / l_s[r0loc + 8];
    #pragma unroll
    for (int nt = 0; nt < 4; nt++) {
        int col = warp_n * 32 + nt * 8 + 2 * t4;
        *(float2*)(out + (size_t)(rowg0 + r0loc)     * Hn + col) =
            make_float2(oacc[nt][0] * inv0, oacc[nt][1] * inv0);
        *(float2*)(out + (size_t)(rowg0 + r0loc + 8) * Hn + col) =
            make_float2(oacc[nt][2] * inv1, oacc[nt][3] * inv1);
    }
}

// ---------------------------------------------------------------------------
extern "C" void kernel_launch(void* const* d_in, const int* in_sizes, int n_in,
                              void* d_out, int out_size)
{
    const float* x  = (const float*)d_in[0];
    const float* Wq = (const float*)d_in[1];
    const float* Wk = (const float*)d_in[2];
    const float* Wv = (const float*)d_in[3];
    float* out = (float*)d_out;

    cudaFuncSetAttribute(qkv_fused, cudaFuncAttributeMaxDynamicSharedMemorySize, QKV_SMEM);
    cudaFuncSetAttribute(attn_bf16, cudaFuncAttributeMaxDynamicSharedMemorySize, ATTN_SMEM);

    conv_w<<<288, 256>>>(Wq, Wk, Wv);
    qkv_fused<<<512, 256, QKV_SMEM>>>(x);
    attn_bf16<<<dim3(4, Bn), 256, ATTN_SMEM>>>(out);
}